// round 1
// baseline (speedup 1.0000x reference)
#include <cuda_runtime.h>

#define NN   50000
#define NE   800000
#define FEAT 16
#define HID  128
#define NL   4
#define NG   1024
#define OD   12

// ---------------- scratch (device globals; no allocations allowed) ----------
__device__ float g_h[NN * HID];     // node features (layer input)
__device__ float g_hw[NN * HID];    // h @ W (pre-aggregation), also embed tmp
__device__ float g_agg[NN * HID];   // aggregation accumulator
__device__ float g_deg[NN];
__device__ float g_dinv[NN];
__device__ float g_pool[NG * HID];
__device__ float g_cnt[NG];

// ---------------- utility kernels ------------------------------------------
__global__ void k_zero() {
    int i = blockIdx.x * blockDim.x + threadIdx.x;
    if (i < NG * HID) g_pool[i] = 0.f;
    if (i < NN)       g_deg[i]  = 0.f;
    if (i < NG)       g_cnt[i]  = 0.f;
}

__global__ void k_deg(const int* __restrict__ ei) {
    int e = blockIdx.x * blockDim.x + threadIdx.x;
    if (e < NE) atomicAdd(&g_deg[ei[NE + e]], 1.f);
}

__global__ void k_dinv() {
    int i = blockIdx.x * blockDim.x + threadIdx.x;
    if (i < NN) g_dinv[i] = rsqrtf(g_deg[i] + 1.f);
}

// ---------------- embed layer 1: tmp = relu(x @ W_e1 + b_e1), K=16 ---------
__global__ void k_embed1(const float* __restrict__ x,
                         const float* __restrict__ W,
                         const float* __restrict__ b) {
    int t  = blockIdx.x * blockDim.x + threadIdx.x;
    int n  = t >> 4;       // node
    int cg = t & 15;       // column group of 8
    if (n >= NN) return;
    float acc[8];
#pragma unroll
    for (int j = 0; j < 8; j++) acc[j] = b[cg * 8 + j];
#pragma unroll
    for (int k = 0; k < FEAT; k++) {
        float xv = x[n * FEAT + k];
#pragma unroll
        for (int j = 0; j < 8; j++)
            acc[j] += xv * W[k * HID + cg * 8 + j];
    }
    float4 o0 = make_float4(fmaxf(acc[0], 0.f), fmaxf(acc[1], 0.f),
                            fmaxf(acc[2], 0.f), fmaxf(acc[3], 0.f));
    float4 o1 = make_float4(fmaxf(acc[4], 0.f), fmaxf(acc[5], 0.f),
                            fmaxf(acc[6], 0.f), fmaxf(acc[7], 0.f));
    float4* out = reinterpret_cast<float4*>(&g_hw[n * HID + cg * 8]);
    out[0] = o0;
    out[1] = o1;
}

// ---------------- generic 128-wide GEMM: C = A@W (+bias), C2 = C*dinv^2 ----
// A: [N,128] row-major, W: [128,128] row-major.
// Block: 128 rows x 128 cols, 256 threads, each thread an 8x8 micro-tile.
__global__ void __launch_bounds__(256)
k_gemm(const float* __restrict__ A, const float* __restrict__ W,
       const float* __restrict__ bias,
       float* __restrict__ C, float* __restrict__ C2, int N) {
    __shared__ float As[16][128];   // [k][row] (transposed tile)
    __shared__ float Bs[16][128];   // [k][col]

    const int tid  = threadIdx.x;
    const int tx   = tid & 15;      // col group (8 cols)
    const int ty   = tid >> 4;      // row group (8 rows)
    const int row0 = blockIdx.x * 128;

    float acc[8][8];
#pragma unroll
    for (int i = 0; i < 8; i++)
#pragma unroll
        for (int j = 0; j < 8; j++) acc[i][j] = 0.f;

    for (int k0 = 0; k0 < HID; k0 += 16) {
#pragma unroll
        for (int t = 0; t < 2; t++) {
            int idx = tid * 2 + t;            // 0..511
            // A tile: rows row0..+127, k-cols k0..+15 (store transposed)
            int r = idx >> 2;                 // 0..127
            int c = idx & 3;                  // float4 slot within 16 k's
            float4 fa = make_float4(0.f, 0.f, 0.f, 0.f);
            int row = row0 + r;
            if (row < N)
                fa = reinterpret_cast<const float4*>(A)[row * 32 + (k0 >> 2) + c];
            As[c * 4 + 0][r] = fa.x;
            As[c * 4 + 1][r] = fa.y;
            As[c * 4 + 2][r] = fa.z;
            As[c * 4 + 3][r] = fa.w;
            // W tile: k-rows k0..+15, all 128 cols
            int kr = idx >> 5;                // 0..15
            int cq = idx & 31;                // float4 col
            reinterpret_cast<float4*>(&Bs[kr][0])[cq] =
                reinterpret_cast<const float4*>(W)[(k0 + kr) * 32 + cq];
        }
        __syncthreads();

#pragma unroll
        for (int kk = 0; kk < 16; kk++) {
            float4 a0 = *reinterpret_cast<const float4*>(&As[kk][ty * 8]);
            float4 a1 = *reinterpret_cast<const float4*>(&As[kk][ty * 8 + 4]);
            float4 b0 = *reinterpret_cast<const float4*>(&Bs[kk][tx * 8]);
            float4 b1 = *reinterpret_cast<const float4*>(&Bs[kk][tx * 8 + 4]);
            float a[8] = {a0.x, a0.y, a0.z, a0.w, a1.x, a1.y, a1.z, a1.w};
            float b[8] = {b0.x, b0.y, b0.z, b0.w, b1.x, b1.y, b1.z, b1.w};
#pragma unroll
            for (int i = 0; i < 8; i++)
#pragma unroll
                for (int j = 0; j < 8; j++)
                    acc[i][j] += a[i] * b[j];
        }
        __syncthreads();
    }

#pragma unroll
    for (int i = 0; i < 8; i++) {
        int row = row0 + ty * 8 + i;
        if (row >= N) continue;
        float d  = g_dinv[row];
        float d2 = d * d;
#pragma unroll
        for (int jj = 0; jj < 2; jj++) {
            int col = tx * 8 + jj * 4;
            float4 v;
            v.x = acc[i][jj * 4 + 0];
            v.y = acc[i][jj * 4 + 1];
            v.z = acc[i][jj * 4 + 2];
            v.w = acc[i][jj * 4 + 3];
            if (bias) {
                const float4 bb = *reinterpret_cast<const float4*>(&bias[col]);
                v.x += bb.x; v.y += bb.y; v.z += bb.z; v.w += bb.w;
            }
            *reinterpret_cast<float4*>(&C[row * HID + col]) = v;
            if (C2) {
                float4 s = make_float4(v.x * d2, v.y * d2, v.z * d2, v.w * d2);
                *reinterpret_cast<float4*>(&C2[row * HID + col]) = s;
            }
        }
    }
}

// ---------------- edge scatter: agg[dst] += hw[src] * dinv[s]*dinv[d] ------
__global__ void k_edges(const int* __restrict__ ei) {
    int t = blockIdx.x * blockDim.x + threadIdx.x;
    int e = t >> 5;
    int l = t & 31;
    if (e >= NE) return;
    int s = ei[e];
    int d = ei[NE + e];
    float norm = g_dinv[s] * g_dinv[d];
    float4 v = reinterpret_cast<const float4*>(g_hw)[s * 32 + l];
    float* out = &g_agg[d * HID + l * 4];
    atomicAdd(out + 0, v.x * norm);
    atomicAdd(out + 1, v.y * norm);
    atomicAdd(out + 2, v.z * norm);
    atomicAdd(out + 3, v.w * norm);
}

// ---------------- layer finish: h = relu(agg + b) ---------------------------
__global__ void k_finish(const float* __restrict__ b) {
    int t = blockIdx.x * blockDim.x + threadIdx.x;
    int n = t >> 5;
    int l = t & 31;
    if (n >= NN) return;
    float4 v  = reinterpret_cast<const float4*>(g_agg)[n * 32 + l];
    float4 bb = reinterpret_cast<const float4*>(b)[l];
    v.x = fmaxf(v.x + bb.x, 0.f);
    v.y = fmaxf(v.y + bb.y, 0.f);
    v.z = fmaxf(v.z + bb.z, 0.f);
    v.w = fmaxf(v.w + bb.w, 0.f);
    reinterpret_cast<float4*>(g_h)[n * 32 + l] = v;
}

// ---------------- pooling: segment sums + counts ----------------------------
__global__ void k_pool(const int* __restrict__ bidx) {
    int t = blockIdx.x * blockDim.x + threadIdx.x;
    int n = t >> 5;
    int l = t & 31;
    if (n >= NN) return;
    int g = bidx[n];
    float4 v = reinterpret_cast<const float4*>(g_h)[n * 32 + l];
    float* p = &g_pool[g * HID + l * 4];
    atomicAdd(p + 0, v.x);
    atomicAdd(p + 1, v.y);
    atomicAdd(p + 2, v.z);
    atomicAdd(p + 3, v.w);
    if (l == 0) atomicAdd(&g_cnt[g], 1.f);
}

// ---------------- output head: out = (pool/cnt) @ Wo + bo -------------------
__global__ void k_out(const float* __restrict__ Wo,
                      const float* __restrict__ bo,
                      float* __restrict__ out) {
    int t = blockIdx.x * blockDim.x + threadIdx.x;
    if (t >= NG * OD) return;
    int g = t / OD;
    int o = t % OD;
    float inv = 1.f / fmaxf(g_cnt[g], 1.f);
    float acc = 0.f;
#pragma unroll 8
    for (int k = 0; k < HID; k++)
        acc += g_pool[g * HID + k] * Wo[k * OD + o];
    out[t] = acc * inv + bo[o];
}

// ---------------- launch ----------------------------------------------------
extern "C" void kernel_launch(void* const* d_in, const int* in_sizes, int n_in,
                              void* d_out, int out_size) {
    const float* x    = (const float*)d_in[0];
    const int*   ei   = (const int*)d_in[1];
    // d_in[2] = edge_attr (unused)
    const int*   bidx = (const int*)d_in[3];
    const float* We1  = (const float*)d_in[4];
    const float* be1  = (const float*)d_in[5];
    const float* We2  = (const float*)d_in[6];
    const float* be2  = (const float*)d_in[7];
    const float* Wg   = (const float*)d_in[8];
    const float* bg   = (const float*)d_in[9];
    const float* Wo   = (const float*)d_in[10];
    const float* bo   = (const float*)d_in[11];
    float*       out  = (float*)d_out;

    float *ph, *phw, *pagg;
    cudaGetSymbolAddress((void**)&ph,   g_h);
    cudaGetSymbolAddress((void**)&phw,  g_hw);
    cudaGetSymbolAddress((void**)&pagg, g_agg);

    const int TB = 256;
    // zero deg/pool/cnt
    k_zero<<<(NG * HID + TB - 1) / TB, TB>>>();
    // degrees + dinv
    k_deg<<<(NE + TB - 1) / TB, TB>>>(ei);
    k_dinv<<<(NN + TB - 1) / TB, TB>>>();
    // node embed MLP
    k_embed1<<<(NN * 16 + TB - 1) / TB, TB>>>(x, We1, be1);
    k_gemm<<<(NN + 127) / 128, TB>>>(phw, We2, be2, ph, nullptr, NN);
    // GCN layers
    for (int i = 0; i < NL; i++) {
        k_gemm<<<(NN + 127) / 128, TB>>>(ph, Wg + i * HID * HID, nullptr,
                                         phw, pagg, NN);
        k_edges<<<(NE * 32 + TB - 1) / TB, TB>>>(ei);
        k_finish<<<(NN * 32 + TB - 1) / TB, TB>>>(bg + i * HID);
    }
    // pooling + head
    k_pool<<<(NN * 32 + TB - 1) / TB, TB>>>(bidx);
    k_out<<<(NG * OD + TB - 1) / TB, TB>>>(Wo, bo, out);
}

// round 2
// speedup vs baseline: 1.7268x; 1.7268x over previous
#include <cuda_runtime.h>

#define NN   50000
#define NE   800000
#define FEAT 16
#define HID  128
#define NL   4
#define NG   1024
#define OD   12

// ---------------- scratch (device globals; no allocations allowed) ----------
__device__ float g_h[NN * HID];     // node features (layer input)
__device__ float g_hw[NN * HID];    // h @ W (pre-aggregation), also embed tmp
__device__ float g_agg[NN * HID];   // aggregation accumulator
__device__ float g_deg[NN];
__device__ float g_dinv[NN];
__device__ float g_pool[NG * HID];
__device__ float g_cnt[NG];

// vector atomic add (sm_90+): red.global.add.v4.f32
__device__ __forceinline__ void red_add_f4(float* p, float4 v) {
    asm volatile("red.global.add.v4.f32 [%0], {%1,%2,%3,%4};"
                 :: "l"(p), "f"(v.x), "f"(v.y), "f"(v.z), "f"(v.w)
                 : "memory");
}

// ---------------- utility kernels ------------------------------------------
__global__ void k_zero() {
    int i = blockIdx.x * blockDim.x + threadIdx.x;
    if (i < NG * HID) g_pool[i] = 0.f;
    if (i < NN)       g_deg[i]  = 0.f;
    if (i < NG)       g_cnt[i]  = 0.f;
}

__global__ void k_deg(const int* __restrict__ ei) {
    int e = blockIdx.x * blockDim.x + threadIdx.x;
    if (e < NE) atomicAdd(&g_deg[ei[NE + e]], 1.f);
}

__global__ void k_dinv() {
    int i = blockIdx.x * blockDim.x + threadIdx.x;
    if (i < NN) g_dinv[i] = rsqrtf(g_deg[i] + 1.f);
}

// ---------------- embed layer 1: hw = relu(x @ W_e1 + b_e1), K=16 ----------
// Block: 256 threads = 16 nodes x 16 col-groups. W staged in shared (8KB),
// x tile staged in shared (1KB). All compute reads hit smem broadcast paths.
__global__ void __launch_bounds__(256)
k_embed1(const float* __restrict__ x,
         const float* __restrict__ W,
         const float* __restrict__ b) {
    __shared__ float Ws[FEAT][HID];   // 16x128
    __shared__ float xs[16][FEAT];    // 16 nodes x 16 feats

    const int tid = threadIdx.x;
    const int n0  = blockIdx.x * 16;

    // load W: 2048 floats / 256 threads = 2 float4 each
    {
        const float4* Wv = reinterpret_cast<const float4*>(W);
        float4* Wsv = reinterpret_cast<float4*>(&Ws[0][0]);
        Wsv[tid]       = Wv[tid];
        Wsv[tid + 256] = Wv[tid + 256];
    }
    // load x tile: 16 nodes x 16 feats = 64 float4; first 64 threads
    if (tid < 64) {
        int node = n0 + (tid >> 2);
        float4 v = make_float4(0.f, 0.f, 0.f, 0.f);
        if (node < NN)
            v = reinterpret_cast<const float4*>(x)[node * 4 + (tid & 3)];
        reinterpret_cast<float4*>(&xs[0][0])[tid] = v;
    }
    __syncthreads();

    const int li = tid >> 4;       // local node 0..15
    const int cg = tid & 15;       // col group of 8
    const int node = n0 + li;
    if (node >= NN) return;

    float acc[8];
#pragma unroll
    for (int j = 0; j < 8; j++) acc[j] = b[cg * 8 + j];
#pragma unroll
    for (int k = 0; k < FEAT; k++) {
        float xv = xs[li][k];
        float4 w0 = *reinterpret_cast<const float4*>(&Ws[k][cg * 8]);
        float4 w1 = *reinterpret_cast<const float4*>(&Ws[k][cg * 8 + 4]);
        acc[0] += xv * w0.x; acc[1] += xv * w0.y;
        acc[2] += xv * w0.z; acc[3] += xv * w0.w;
        acc[4] += xv * w1.x; acc[5] += xv * w1.y;
        acc[6] += xv * w1.z; acc[7] += xv * w1.w;
    }
    float4 o0 = make_float4(fmaxf(acc[0], 0.f), fmaxf(acc[1], 0.f),
                            fmaxf(acc[2], 0.f), fmaxf(acc[3], 0.f));
    float4 o1 = make_float4(fmaxf(acc[4], 0.f), fmaxf(acc[5], 0.f),
                            fmaxf(acc[6], 0.f), fmaxf(acc[7], 0.f));
    float4* out = reinterpret_cast<float4*>(&g_hw[node * HID + cg * 8]);
    out[0] = o0;
    out[1] = o1;
}

// ---------------- generic 128-wide GEMM: C = A@W (+bias), C2 = C*dinv^2 ----
__global__ void __launch_bounds__(256)
k_gemm(const float* __restrict__ A, const float* __restrict__ W,
       const float* __restrict__ bias,
       float* __restrict__ C, float* __restrict__ C2, int N) {
    __shared__ float As[16][128];   // [k][row] (transposed tile)
    __shared__ float Bs[16][128];   // [k][col]

    const int tid  = threadIdx.x;
    const int tx   = tid & 15;      // col group (8 cols)
    const int ty   = tid >> 4;      // row group (8 rows)
    const int row0 = blockIdx.x * 128;

    float acc[8][8];
#pragma unroll
    for (int i = 0; i < 8; i++)
#pragma unroll
        for (int j = 0; j < 8; j++) acc[i][j] = 0.f;

    for (int k0 = 0; k0 < HID; k0 += 16) {
#pragma unroll
        for (int t = 0; t < 2; t++) {
            int idx = tid * 2 + t;            // 0..511
            int r = idx >> 2;                 // 0..127
            int c = idx & 3;                  // float4 slot within 16 k's
            float4 fa = make_float4(0.f, 0.f, 0.f, 0.f);
            int row = row0 + r;
            if (row < N)
                fa = reinterpret_cast<const float4*>(A)[row * 32 + (k0 >> 2) + c];
            As[c * 4 + 0][r] = fa.x;
            As[c * 4 + 1][r] = fa.y;
            As[c * 4 + 2][r] = fa.z;
            As[c * 4 + 3][r] = fa.w;
            int kr = idx >> 5;                // 0..15
            int cq = idx & 31;                // float4 col
            reinterpret_cast<float4*>(&Bs[kr][0])[cq] =
                reinterpret_cast<const float4*>(W)[(k0 + kr) * 32 + cq];
        }
        __syncthreads();

#pragma unroll
        for (int kk = 0; kk < 16; kk++) {
            float4 a0 = *reinterpret_cast<const float4*>(&As[kk][ty * 8]);
            float4 a1 = *reinterpret_cast<const float4*>(&As[kk][ty * 8 + 4]);
            float4 b0 = *reinterpret_cast<const float4*>(&Bs[kk][tx * 8]);
            float4 b1 = *reinterpret_cast<const float4*>(&Bs[kk][tx * 8 + 4]);
            float a[8] = {a0.x, a0.y, a0.z, a0.w, a1.x, a1.y, a1.z, a1.w};
            float b[8] = {b0.x, b0.y, b0.z, b0.w, b1.x, b1.y, b1.z, b1.w};
#pragma unroll
            for (int i = 0; i < 8; i++)
#pragma unroll
                for (int j = 0; j < 8; j++)
                    acc[i][j] += a[i] * b[j];
        }
        __syncthreads();
    }

#pragma unroll
    for (int i = 0; i < 8; i++) {
        int row = row0 + ty * 8 + i;
        if (row >= N) continue;
        float d  = g_dinv[row];
        float d2 = d * d;
#pragma unroll
        for (int jj = 0; jj < 2; jj++) {
            int col = tx * 8 + jj * 4;
            float4 v;
            v.x = acc[i][jj * 4 + 0];
            v.y = acc[i][jj * 4 + 1];
            v.z = acc[i][jj * 4 + 2];
            v.w = acc[i][jj * 4 + 3];
            if (bias) {
                const float4 bb = *reinterpret_cast<const float4*>(&bias[col]);
                v.x += bb.x; v.y += bb.y; v.z += bb.z; v.w += bb.w;
            }
            *reinterpret_cast<float4*>(&C[row * HID + col]) = v;
            if (C2) {
                float4 s = make_float4(v.x * d2, v.y * d2, v.z * d2, v.w * d2);
                *reinterpret_cast<float4*>(&C2[row * HID + col]) = s;
            }
        }
    }
}

// ---------------- edge scatter: agg[dst] += hw[src] * dinv[s]*dinv[d] ------
// One warp per edge; each lane handles 4 floats via one vector red.
__global__ void k_edges(const int* __restrict__ ei) {
    int t = blockIdx.x * blockDim.x + threadIdx.x;
    int e = t >> 5;
    int l = t & 31;
    if (e >= NE) return;
    int s = ei[e];
    int d = ei[NE + e];
    float norm = g_dinv[s] * g_dinv[d];
    float4 v = reinterpret_cast<const float4*>(g_hw)[s * 32 + l];
    v.x *= norm; v.y *= norm; v.z *= norm; v.w *= norm;
    red_add_f4(&g_agg[d * HID + l * 4], v);
}

// ---------------- layer finish: h = relu(agg + b) ---------------------------
__global__ void k_finish(const float* __restrict__ b) {
    int t = blockIdx.x * blockDim.x + threadIdx.x;
    int n = t >> 5;
    int l = t & 31;
    if (n >= NN) return;
    float4 v  = reinterpret_cast<const float4*>(g_agg)[n * 32 + l];
    float4 bb = reinterpret_cast<const float4*>(b)[l];
    v.x = fmaxf(v.x + bb.x, 0.f);
    v.y = fmaxf(v.y + bb.y, 0.f);
    v.z = fmaxf(v.z + bb.z, 0.f);
    v.w = fmaxf(v.w + bb.w, 0.f);
    reinterpret_cast<float4*>(g_h)[n * 32 + l] = v;
}

// ---------------- pooling: segment sums + counts ----------------------------
__global__ void k_pool(const int* __restrict__ bidx) {
    int t = blockIdx.x * blockDim.x + threadIdx.x;
    int n = t >> 5;
    int l = t & 31;
    if (n >= NN) return;
    int g = bidx[n];
    float4 v = reinterpret_cast<const float4*>(g_h)[n * 32 + l];
    red_add_f4(&g_pool[g * HID + l * 4], v);
    if (l == 0) atomicAdd(&g_cnt[g], 1.f);
}

// ---------------- output head: out = (pool/cnt) @ Wo + bo -------------------
__global__ void k_out(const float* __restrict__ Wo,
                      const float* __restrict__ bo,
                      float* __restrict__ out) {
    int t = blockIdx.x * blockDim.x + threadIdx.x;
    if (t >= NG * OD) return;
    int g = t / OD;
    int o = t % OD;
    float inv = 1.f / fmaxf(g_cnt[g], 1.f);
    float acc = 0.f;
#pragma unroll 8
    for (int k = 0; k < HID; k++)
        acc += g_pool[g * HID + k] * Wo[k * OD + o];
    out[t] = acc * inv + bo[o];
}

// ---------------- launch ----------------------------------------------------
extern "C" void kernel_launch(void* const* d_in, const int* in_sizes, int n_in,
                              void* d_out, int out_size) {
    const float* x    = (const float*)d_in[0];
    const int*   ei   = (const int*)d_in[1];
    // d_in[2] = edge_attr (unused)
    const int*   bidx = (const int*)d_in[3];
    const float* We1  = (const float*)d_in[4];
    const float* be1  = (const float*)d_in[5];
    const float* We2  = (const float*)d_in[6];
    const float* be2  = (const float*)d_in[7];
    const float* Wg   = (const float*)d_in[8];
    const float* bg   = (const float*)d_in[9];
    const float* Wo   = (const float*)d_in[10];
    const float* bo   = (const float*)d_in[11];
    float*       out  = (float*)d_out;

    float *ph, *phw, *pagg;
    cudaGetSymbolAddress((void**)&ph,   g_h);
    cudaGetSymbolAddress((void**)&phw,  g_hw);
    cudaGetSymbolAddress((void**)&pagg, g_agg);

    const int TB = 256;
    k_zero<<<(NG * HID + TB - 1) / TB, TB>>>();
    k_deg<<<(NE + TB - 1) / TB, TB>>>(ei);
    k_dinv<<<(NN + TB - 1) / TB, TB>>>();
    // node embed MLP
    k_embed1<<<(NN + 15) / 16, TB>>>(x, We1, be1);
    k_gemm<<<(NN + 127) / 128, TB>>>(phw, We2, be2, ph, nullptr, NN);
    // GCN layers
    for (int i = 0; i < NL; i++) {
        k_gemm<<<(NN + 127) / 128, TB>>>(ph, Wg + i * HID * HID, nullptr,
                                         phw, pagg, NN);
        k_edges<<<(NE * 32 + TB - 1) / TB, TB>>>(ei);
        k_finish<<<(NN * 32 + TB - 1) / TB, TB>>>(bg + i * HID);
    }
    // pooling + head
    k_pool<<<(NN * 32 + TB - 1) / TB, TB>>>(bidx);
    k_out<<<(NG * OD + TB - 1) / TB, TB>>>(Wo, bo, out);
}

// round 3
// speedup vs baseline: 2.8189x; 1.6324x over previous
#include <cuda_runtime.h>

#define NN   50000
#define NE   800000
#define FEAT 16
#define HID  128
#define NL   4
#define NG   1024
#define OD   12
#define NBLK ((NN + 1023) / 1024)   // scan blocks = 49

// ---------------- scratch (device globals; no allocations allowed) ----------
__device__ float g_h[NN * HID];     // node features (layer input)
__device__ float g_hw[NN * HID];    // h @ W (pre-aggregation), also embed tmp
__device__ float g_dinv[NN];
__device__ float g_pool[NG * HID];
__device__ float g_cnt[NG];
__device__ int   g_degi[NN];
__device__ int   g_rowptr[NN + 1];  // CSR row pointers (by dst)
__device__ int   g_fillcnt[NN];
__device__ int   g_csr[NE];         // src indices grouped by dst
__device__ int   g_bsum[64];        // scan block sums

// vector atomic add (sm_90+): red.global.add.v4.f32
__device__ __forceinline__ void red_add_f4(float* p, float4 v) {
    asm volatile("red.global.add.v4.f32 [%0], {%1,%2,%3,%4};"
                 :: "l"(p), "f"(v.x), "f"(v.y), "f"(v.z), "f"(v.w)
                 : "memory");
}

// ---------------- init / CSR build -----------------------------------------
__global__ void k_zero() {
    int i = blockIdx.x * blockDim.x + threadIdx.x;
    if (i < NG * HID) g_pool[i] = 0.f;
    if (i < NG)       g_cnt[i]  = 0.f;
    if (i < NN) { g_degi[i] = 0; g_fillcnt[i] = 0; }
}

__global__ void k_deg(const int* __restrict__ ei) {
    int e = blockIdx.x * blockDim.x + threadIdx.x;
    if (e < NE) atomicAdd(&g_degi[ei[NE + e]], 1);
}

// block-level inclusive scan of degrees (1024/block); rowptr holds inclusive
__global__ void __launch_bounds__(1024)
k_scan1() {
    __shared__ int sh[1024];
    int t = threadIdx.x;
    int i = blockIdx.x * 1024 + t;
    int d = (i < NN) ? g_degi[i] : 0;
    sh[t] = d;
    __syncthreads();
#pragma unroll
    for (int off = 1; off < 1024; off <<= 1) {
        int v = (t >= off) ? sh[t - off] : 0;
        __syncthreads();
        sh[t] += v;
        __syncthreads();
    }
    if (i < NN) g_rowptr[i] = sh[t];
    if (t == 1023) g_bsum[blockIdx.x] = sh[t];
}

__global__ void k_scan2() {
    if (threadIdx.x == 0) {
        int run = 0;
#pragma unroll
        for (int i = 0; i < NBLK; i++) {
            int v = g_bsum[i];
            g_bsum[i] = run;
            run += v;
        }
    }
}

__global__ void k_scan3() {
    int i = blockIdx.x * blockDim.x + threadIdx.x;
    if (i < NN) {
        int incl = g_rowptr[i];
        int d    = g_degi[i];
        g_rowptr[i] = incl - d + g_bsum[i >> 10];  // exclusive + block offset
        g_dinv[i]   = rsqrtf((float)d + 1.f);
    }
    if (i == 0) g_rowptr[NN] = NE;
}

__global__ void k_fill(const int* __restrict__ ei) {
    int e = blockIdx.x * blockDim.x + threadIdx.x;
    if (e >= NE) return;
    int s = ei[e];
    int d = ei[NE + e];
    int pos = g_rowptr[d] + atomicAdd(&g_fillcnt[d], 1);
    g_csr[pos] = s;
}

// ---------------- embed layer 1: hw = relu(x @ W_e1 + b_e1), K=16 ----------
// 256 threads: 16 col-groups x 16 row-groups; each thread does 2 nodes x 8 cols.
__global__ void __launch_bounds__(256)
k_embed1(const float* __restrict__ x,
         const float* __restrict__ W,
         const float* __restrict__ b) {
    __shared__ float Ws[FEAT][HID];   // 16x128 = 8KB
    __shared__ float xs[32][FEAT];    // 32 nodes x 16 feats = 2KB

    const int tid = threadIdx.x;
    const int n0  = blockIdx.x * 32;

    {
        const float4* Wv = reinterpret_cast<const float4*>(W);
        float4* Wsv = reinterpret_cast<float4*>(&Ws[0][0]);
        Wsv[tid]       = Wv[tid];
        Wsv[tid + 256] = Wv[tid + 256];
    }
    if (tid < 128) {
        int node = n0 + (tid >> 2);
        float4 v = make_float4(0.f, 0.f, 0.f, 0.f);
        if (node < NN)
            v = reinterpret_cast<const float4*>(x)[node * 4 + (tid & 3)];
        reinterpret_cast<float4*>(&xs[0][0])[tid] = v;
    }
    __syncthreads();

    const int rg = tid >> 4;       // row group: 2 nodes
    const int cg = tid & 15;       // col group of 8
    float acc[2][8];
    float bb[8];
#pragma unroll
    for (int j = 0; j < 8; j++) bb[j] = b[cg * 8 + j];
#pragma unroll
    for (int v = 0; v < 2; v++)
#pragma unroll
        for (int j = 0; j < 8; j++) acc[v][j] = bb[j];

#pragma unroll
    for (int k = 0; k < FEAT; k++) {
        float4 w0 = *reinterpret_cast<const float4*>(&Ws[k][cg * 8]);
        float4 w1 = *reinterpret_cast<const float4*>(&Ws[k][cg * 8 + 4]);
        float xv0 = xs[rg * 2 + 0][k];
        float xv1 = xs[rg * 2 + 1][k];
        acc[0][0] += xv0 * w0.x; acc[0][1] += xv0 * w0.y;
        acc[0][2] += xv0 * w0.z; acc[0][3] += xv0 * w0.w;
        acc[0][4] += xv0 * w1.x; acc[0][5] += xv0 * w1.y;
        acc[0][6] += xv0 * w1.z; acc[0][7] += xv0 * w1.w;
        acc[1][0] += xv1 * w0.x; acc[1][1] += xv1 * w0.y;
        acc[1][2] += xv1 * w0.z; acc[1][3] += xv1 * w0.w;
        acc[1][4] += xv1 * w1.x; acc[1][5] += xv1 * w1.y;
        acc[1][6] += xv1 * w1.z; acc[1][7] += xv1 * w1.w;
    }
#pragma unroll
    for (int v = 0; v < 2; v++) {
        int node = n0 + rg * 2 + v;
        if (node >= NN) continue;
        float4 o0 = make_float4(fmaxf(acc[v][0], 0.f), fmaxf(acc[v][1], 0.f),
                                fmaxf(acc[v][2], 0.f), fmaxf(acc[v][3], 0.f));
        float4 o1 = make_float4(fmaxf(acc[v][4], 0.f), fmaxf(acc[v][5], 0.f),
                                fmaxf(acc[v][6], 0.f), fmaxf(acc[v][7], 0.f));
        float4* out = reinterpret_cast<float4*>(&g_hw[node * HID + cg * 8]);
        out[0] = o0;
        out[1] = o1;
    }
}

// ---------------- generic 128-wide GEMM: C = A@W (+bias) --------------------
__global__ void __launch_bounds__(256)
k_gemm(const float* __restrict__ A, const float* __restrict__ W,
       const float* __restrict__ bias, float* __restrict__ C, int N) {
    __shared__ float As[16][128];   // [k][row]
    __shared__ float Bs[16][128];   // [k][col]

    const int tid  = threadIdx.x;
    const int tx   = tid & 15;
    const int ty   = tid >> 4;
    const int row0 = blockIdx.x * 128;

    float acc[8][8];
#pragma unroll
    for (int i = 0; i < 8; i++)
#pragma unroll
        for (int j = 0; j < 8; j++) acc[i][j] = 0.f;

    for (int k0 = 0; k0 < HID; k0 += 16) {
#pragma unroll
        for (int t = 0; t < 2; t++) {
            int idx = tid * 2 + t;
            int r = idx >> 2;
            int c = idx & 3;
            float4 fa = make_float4(0.f, 0.f, 0.f, 0.f);
            int row = row0 + r;
            if (row < N)
                fa = reinterpret_cast<const float4*>(A)[row * 32 + (k0 >> 2) + c];
            As[c * 4 + 0][r] = fa.x;
            As[c * 4 + 1][r] = fa.y;
            As[c * 4 + 2][r] = fa.z;
            As[c * 4 + 3][r] = fa.w;
            int kr = idx >> 5;
            int cq = idx & 31;
            reinterpret_cast<float4*>(&Bs[kr][0])[cq] =
                reinterpret_cast<const float4*>(W)[(k0 + kr) * 32 + cq];
        }
        __syncthreads();

#pragma unroll
        for (int kk = 0; kk < 16; kk++) {
            float4 a0 = *reinterpret_cast<const float4*>(&As[kk][ty * 8]);
            float4 a1 = *reinterpret_cast<const float4*>(&As[kk][ty * 8 + 4]);
            float4 b0 = *reinterpret_cast<const float4*>(&Bs[kk][tx * 8]);
            float4 b1 = *reinterpret_cast<const float4*>(&Bs[kk][tx * 8 + 4]);
            float a[8] = {a0.x, a0.y, a0.z, a0.w, a1.x, a1.y, a1.z, a1.w};
            float b[8] = {b0.x, b0.y, b0.z, b0.w, b1.x, b1.y, b1.z, b1.w};
#pragma unroll
            for (int i = 0; i < 8; i++)
#pragma unroll
                for (int j = 0; j < 8; j++)
                    acc[i][j] += a[i] * b[j];
        }
        __syncthreads();
    }

#pragma unroll
    for (int i = 0; i < 8; i++) {
        int row = row0 + ty * 8 + i;
        if (row >= N) continue;
#pragma unroll
        for (int jj = 0; jj < 2; jj++) {
            int col = tx * 8 + jj * 4;
            float4 v;
            v.x = acc[i][jj * 4 + 0];
            v.y = acc[i][jj * 4 + 1];
            v.z = acc[i][jj * 4 + 2];
            v.w = acc[i][jj * 4 + 3];
            if (bias) {
                const float4 bb = *reinterpret_cast<const float4*>(&bias[col]);
                v.x += bb.x; v.y += bb.y; v.z += bb.z; v.w += bb.w;
            }
            *reinterpret_cast<float4*>(&C[row * HID + col]) = v;
        }
    }
}

// ---------------- fused CSR SpMM: h = relu(agg + self + b), opt. pooling ----
// One warp per dst node; lane l owns feature floats [4l, 4l+4).
__global__ void __launch_bounds__(256)
k_spmm(const float* __restrict__ bias, const int* __restrict__ bidx,
       int do_pool) {
    int gt = blockIdx.x * blockDim.x + threadIdx.x;
    int n  = gt >> 5;
    int l  = gt & 31;
    if (n >= NN) return;

    const float4* hw4 = reinterpret_cast<const float4*>(g_hw);
    float dn = g_dinv[n];
    int start = g_rowptr[n];
    int end   = g_rowptr[n + 1];

    // self-loop term
    float4 hv = hw4[n * 32 + l];
    float d2 = dn * dn;
    float4 acc = make_float4(hv.x * d2, hv.y * d2, hv.z * d2, hv.w * d2);

    for (int base = start; base < end; base += 32) {
        int idx = base + l;
        int s   = 0;
        float dv = 0.f;
        if (idx < end) {
            s  = g_csr[idx];
            dv = g_dinv[s] * dn;
        }
        int m = min(32, end - base);
        for (int j = 0; j < m; j++) {
            int   ss = __shfl_sync(0xffffffff, s, j);
            float nm = __shfl_sync(0xffffffff, dv, j);
            float4 v = hw4[ss * 32 + l];
            acc.x += v.x * nm; acc.y += v.y * nm;
            acc.z += v.z * nm; acc.w += v.w * nm;
        }
    }

    float4 bb = reinterpret_cast<const float4*>(bias)[l];
    acc.x = fmaxf(acc.x + bb.x, 0.f);
    acc.y = fmaxf(acc.y + bb.y, 0.f);
    acc.z = fmaxf(acc.z + bb.z, 0.f);
    acc.w = fmaxf(acc.w + bb.w, 0.f);
    reinterpret_cast<float4*>(g_h)[n * 32 + l] = acc;

    if (do_pool) {
        int g = bidx[n];
        red_add_f4(&g_pool[g * HID + l * 4], acc);
        if (l == 0) atomicAdd(&g_cnt[g], 1.f);
    }
}

// ---------------- output head: out = (pool/cnt) @ Wo + bo -------------------
__global__ void k_out(const float* __restrict__ Wo,
                      const float* __restrict__ bo,
                      float* __restrict__ out) {
    int t = blockIdx.x * blockDim.x + threadIdx.x;
    if (t >= NG * OD) return;
    int g = t / OD;
    int o = t % OD;
    float inv = 1.f / fmaxf(g_cnt[g], 1.f);
    float acc = 0.f;
#pragma unroll 8
    for (int k = 0; k < HID; k++)
        acc += g_pool[g * HID + k] * Wo[k * OD + o];
    out[t] = acc * inv + bo[o];
}

// ---------------- launch ----------------------------------------------------
extern "C" void kernel_launch(void* const* d_in, const int* in_sizes, int n_in,
                              void* d_out, int out_size) {
    const float* x    = (const float*)d_in[0];
    const int*   ei   = (const int*)d_in[1];
    // d_in[2] = edge_attr (unused)
    const int*   bidx = (const int*)d_in[3];
    const float* We1  = (const float*)d_in[4];
    const float* be1  = (const float*)d_in[5];
    const float* We2  = (const float*)d_in[6];
    const float* be2  = (const float*)d_in[7];
    const float* Wg   = (const float*)d_in[8];
    const float* bg   = (const float*)d_in[9];
    const float* Wo   = (const float*)d_in[10];
    const float* bo   = (const float*)d_in[11];
    float*       out  = (float*)d_out;

    float *ph, *phw;
    cudaGetSymbolAddress((void**)&ph,  g_h);
    cudaGetSymbolAddress((void**)&phw, g_hw);

    const int TB = 256;
    // init + CSR build
    k_zero <<<(NG * HID + TB - 1) / TB, TB>>>();
    k_deg  <<<(NE + TB - 1) / TB, TB>>>(ei);
    k_scan1<<<NBLK, 1024>>>();
    k_scan2<<<1, 32>>>();
    k_scan3<<<(NN + TB - 1) / TB, TB>>>();
    k_fill <<<(NE + TB - 1) / TB, TB>>>(ei);
    // node embed MLP
    k_embed1<<<(NN + 31) / 32, TB>>>(x, We1, be1);
    k_gemm<<<(NN + 127) / 128, TB>>>(phw, We2, be2, ph, NN);
    // GCN layers: gemm -> fused spmm (+pool on last)
    for (int i = 0; i < NL; i++) {
        k_gemm<<<(NN + 127) / 128, TB>>>(ph, Wg + i * HID * HID, nullptr,
                                         phw, NN);
        k_spmm<<<(NN * 32 + TB - 1) / TB, TB>>>(bg + i * HID, bidx,
                                                i == NL - 1 ? 1 : 0);
    }
    // head
    k_out<<<(NG * OD + TB - 1) / TB, TB>>>(Wo, bo, out);
}

// round 4
// speedup vs baseline: 2.8317x; 1.0045x over previous
#include <cuda_runtime.h>
#include <cstdint>

#define NN   50000
#define NE   800000
#define FEAT 16
#define HID  128
#define NL   4
#define NG   1024
#define OD   12
#define NBLK ((NN + 1023) / 1024)   // scan blocks = 49

// ---------------- scratch (device globals; no allocations allowed) ----------
__device__ float g_h[NN * HID];
__device__ float g_hw[NN * HID];
__device__ float g_dinv[NN];
__device__ float g_pool[NG * HID];
__device__ float g_cnt[NG];
__device__ int   g_degi[NN];
__device__ int   g_rowptr[NN + 1];
__device__ int   g_fillcnt[NN];
__device__ int   g_csr[NE];
__device__ int   g_bsum[64];

__device__ __forceinline__ void red_add_f4(float* p, float4 v) {
    asm volatile("red.global.add.v4.f32 [%0], {%1,%2,%3,%4};"
                 :: "l"(p), "f"(v.x), "f"(v.y), "f"(v.z), "f"(v.w)
                 : "memory");
}

__device__ __forceinline__ uint32_t f2tf32(float a) {
    uint32_t r;
    asm("cvt.rna.tf32.f32 %0, %1;" : "=r"(r) : "f"(a));
    return r;
}

__device__ __forceinline__ void mma_tf32(float c[4],
                                         uint32_t a0, uint32_t a1,
                                         uint32_t a2, uint32_t a3,
                                         uint32_t b0, uint32_t b1) {
    asm volatile(
        "mma.sync.aligned.m16n8k8.row.col.f32.tf32.tf32.f32 "
        "{%0,%1,%2,%3}, {%4,%5,%6,%7}, {%8,%9}, {%0,%1,%2,%3};"
        : "+f"(c[0]), "+f"(c[1]), "+f"(c[2]), "+f"(c[3])
        : "r"(a0), "r"(a1), "r"(a2), "r"(a3), "r"(b0), "r"(b1));
}

// ---------------- init / CSR build -----------------------------------------
__global__ void k_zero() {
    int i = blockIdx.x * blockDim.x + threadIdx.x;
    if (i < NG * HID) g_pool[i] = 0.f;
    if (i < NG)       g_cnt[i]  = 0.f;
    if (i < NN) { g_degi[i] = 0; g_fillcnt[i] = 0; }
}

__global__ void k_deg(const int* __restrict__ ei) {
    int e = blockIdx.x * blockDim.x + threadIdx.x;
    if (e < NE) atomicAdd(&g_degi[ei[NE + e]], 1);
}

__global__ void __launch_bounds__(1024)
k_scan1() {
    __shared__ int sh[1024];
    int t = threadIdx.x;
    int i = blockIdx.x * 1024 + t;
    int d = (i < NN) ? g_degi[i] : 0;
    sh[t] = d;
    __syncthreads();
#pragma unroll
    for (int off = 1; off < 1024; off <<= 1) {
        int v = (t >= off) ? sh[t - off] : 0;
        __syncthreads();
        sh[t] += v;
        __syncthreads();
    }
    if (i < NN) g_rowptr[i] = sh[t];
    if (t == 1023) g_bsum[blockIdx.x] = sh[t];
}

__global__ void k_scan2() {
    if (threadIdx.x == 0) {
        int run = 0;
#pragma unroll
        for (int i = 0; i < NBLK; i++) {
            int v = g_bsum[i];
            g_bsum[i] = run;
            run += v;
        }
    }
}

__global__ void k_scan3() {
    int i = blockIdx.x * blockDim.x + threadIdx.x;
    if (i < NN) {
        int incl = g_rowptr[i];
        int d    = g_degi[i];
        g_rowptr[i] = incl - d + g_bsum[i >> 10];
        g_dinv[i]   = rsqrtf((float)d + 1.f);
    }
    if (i == 0) g_rowptr[NN] = NE;
}

__global__ void k_fill(const int* __restrict__ ei) {
    int e = blockIdx.x * blockDim.x + threadIdx.x;
    if (e >= NE) return;
    int s = ei[e];
    int d = ei[NE + e];
    int pos = g_rowptr[d] + atomicAdd(&g_fillcnt[d], 1);
    g_csr[pos] = s;
}

// ---------------- embed layer 1: hw = relu(x @ W_e1 + b_e1), K=16 ----------
__global__ void __launch_bounds__(256)
k_embed1(const float* __restrict__ x,
         const float* __restrict__ W,
         const float* __restrict__ b) {
    __shared__ float Ws[FEAT][HID];
    __shared__ float xs[32][FEAT];

    const int tid = threadIdx.x;
    const int n0  = blockIdx.x * 32;

    {
        const float4* Wv = reinterpret_cast<const float4*>(W);
        float4* Wsv = reinterpret_cast<float4*>(&Ws[0][0]);
        Wsv[tid]       = Wv[tid];
        Wsv[tid + 256] = Wv[tid + 256];
    }
    if (tid < 128) {
        int node = n0 + (tid >> 2);
        float4 v = make_float4(0.f, 0.f, 0.f, 0.f);
        if (node < NN)
            v = reinterpret_cast<const float4*>(x)[node * 4 + (tid & 3)];
        reinterpret_cast<float4*>(&xs[0][0])[tid] = v;
    }
    __syncthreads();

    const int rg = tid >> 4;
    const int cg = tid & 15;
    float acc[2][8];
    float bb[8];
#pragma unroll
    for (int j = 0; j < 8; j++) bb[j] = b[cg * 8 + j];
#pragma unroll
    for (int v = 0; v < 2; v++)
#pragma unroll
        for (int j = 0; j < 8; j++) acc[v][j] = bb[j];

#pragma unroll
    for (int k = 0; k < FEAT; k++) {
        float4 w0 = *reinterpret_cast<const float4*>(&Ws[k][cg * 8]);
        float4 w1 = *reinterpret_cast<const float4*>(&Ws[k][cg * 8 + 4]);
        float xv0 = xs[rg * 2 + 0][k];
        float xv1 = xs[rg * 2 + 1][k];
        acc[0][0] += xv0 * w0.x; acc[0][1] += xv0 * w0.y;
        acc[0][2] += xv0 * w0.z; acc[0][3] += xv0 * w0.w;
        acc[0][4] += xv0 * w1.x; acc[0][5] += xv0 * w1.y;
        acc[0][6] += xv0 * w1.z; acc[0][7] += xv0 * w1.w;
        acc[1][0] += xv1 * w0.x; acc[1][1] += xv1 * w0.y;
        acc[1][2] += xv1 * w0.z; acc[1][3] += xv1 * w0.w;
        acc[1][4] += xv1 * w1.x; acc[1][5] += xv1 * w1.y;
        acc[1][6] += xv1 * w1.z; acc[1][7] += xv1 * w1.w;
    }
#pragma unroll
    for (int v = 0; v < 2; v++) {
        int node = n0 + rg * 2 + v;
        if (node >= NN) continue;
        float4 o0 = make_float4(fmaxf(acc[v][0], 0.f), fmaxf(acc[v][1], 0.f),
                                fmaxf(acc[v][2], 0.f), fmaxf(acc[v][3], 0.f));
        float4 o1 = make_float4(fmaxf(acc[v][4], 0.f), fmaxf(acc[v][5], 0.f),
                                fmaxf(acc[v][6], 0.f), fmaxf(acc[v][7], 0.f));
        float4* out = reinterpret_cast<float4*>(&g_hw[node * HID + cg * 8]);
        out[0] = o0;
        out[1] = o1;
    }
}

// ---------------- tensor-core GEMM (3xTF32): C = A@W (+bias) ----------------
// Block: 256 thr = 8 warps; block tile 128x128; warp tile 16x128.
// K chunked by 16, converted to tf32 hi/lo in smem.
__global__ void __launch_bounds__(256)
k_gemm_tc(const float* __restrict__ A, const float* __restrict__ W,
          const float* __restrict__ bias, float* __restrict__ C, int N) {
    __shared__ float sAh[128][17], sAl[128][17];   // [m][k]
    __shared__ float sBh[16][132], sBl[16][132];   // [k][n]

    const int tid  = threadIdx.x;
    const int wid  = tid >> 5;
    const int lane = tid & 31;
    const int grp  = lane >> 2;      // 0..7
    const int tig  = lane & 3;       // 0..3
    const int row0 = blockIdx.x * 128;
    const int wm   = wid * 16;       // warp's m offset in tile

    float c[16][4];
#pragma unroll
    for (int i = 0; i < 16; i++)
#pragma unroll
        for (int j = 0; j < 4; j++) c[i][j] = 0.f;

    for (int kc = 0; kc < HID / 16; kc++) {
        // stage + convert A[128x16] and B[16x128] to tf32 hi/lo
#pragma unroll
        for (int t = 0; t < 2; t++) {
            int idx = tid * 2 + t;           // 0..511
            {   // A
                int r = idx >> 2;            // 0..127
                int q = idx & 3;             // k-quad
                float4 fa = make_float4(0.f, 0.f, 0.f, 0.f);
                int row = row0 + r;
                if (row < N)
                    fa = reinterpret_cast<const float4*>(A)[row * 32 + kc * 4 + q];
                float av[4] = {fa.x, fa.y, fa.z, fa.w};
#pragma unroll
                for (int i = 0; i < 4; i++) {
                    uint32_t hb = f2tf32(av[i]);
                    float hf = __uint_as_float(hb);
                    sAh[r][q * 4 + i] = hf;
                    sAl[r][q * 4 + i] = __uint_as_float(f2tf32(av[i] - hf));
                }
            }
            {   // B
                int kr = idx >> 5;           // 0..15
                int cq = idx & 31;           // float4 col
                float4 fb = reinterpret_cast<const float4*>(W)[(kc * 16 + kr) * 32 + cq];
                float bv[4] = {fb.x, fb.y, fb.z, fb.w};
#pragma unroll
                for (int i = 0; i < 4; i++) {
                    uint32_t hb = f2tf32(bv[i]);
                    float hf = __uint_as_float(hb);
                    sBh[kr][cq * 4 + i] = hf;
                    sBl[kr][cq * 4 + i] = __uint_as_float(f2tf32(bv[i] - hf));
                }
            }
        }
        __syncthreads();

#pragma unroll
        for (int ks = 0; ks < 16; ks += 8) {
            // A fragments (m16 x k8), hi and lo
            uint32_t ah0 = __float_as_uint(sAh[wm + grp    ][ks + tig    ]);
            uint32_t ah1 = __float_as_uint(sAh[wm + grp + 8][ks + tig    ]);
            uint32_t ah2 = __float_as_uint(sAh[wm + grp    ][ks + tig + 4]);
            uint32_t ah3 = __float_as_uint(sAh[wm + grp + 8][ks + tig + 4]);
            uint32_t al0 = __float_as_uint(sAl[wm + grp    ][ks + tig    ]);
            uint32_t al1 = __float_as_uint(sAl[wm + grp + 8][ks + tig    ]);
            uint32_t al2 = __float_as_uint(sAl[wm + grp    ][ks + tig + 4]);
            uint32_t al3 = __float_as_uint(sAl[wm + grp + 8][ks + tig + 4]);

#pragma unroll
            for (int nt = 0; nt < 16; nt++) {
                int ncol = nt * 8 + grp;
                uint32_t bh0 = __float_as_uint(sBh[ks + tig    ][ncol]);
                uint32_t bh1 = __float_as_uint(sBh[ks + tig + 4][ncol]);
                uint32_t bl0 = __float_as_uint(sBl[ks + tig    ][ncol]);
                uint32_t bl1 = __float_as_uint(sBl[ks + tig + 4][ncol]);
                mma_tf32(c[nt], ah0, ah1, ah2, ah3, bl0, bl1);   // hi*lo
                mma_tf32(c[nt], al0, al1, al2, al3, bh0, bh1);   // lo*hi
                mma_tf32(c[nt], ah0, ah1, ah2, ah3, bh0, bh1);   // hi*hi
            }
        }
        __syncthreads();
    }

    // epilogue: c[nt] rows = row0+wm+grp(+8), cols = nt*8 + 2*tig + {0,1}
    int r_lo = row0 + wm + grp;
    int r_hi = r_lo + 8;
#pragma unroll
    for (int nt = 0; nt < 16; nt++) {
        int col = nt * 8 + 2 * tig;
        float2 v0 = make_float2(c[nt][0], c[nt][1]);
        float2 v1 = make_float2(c[nt][2], c[nt][3]);
        if (bias) {
            float2 bb = *reinterpret_cast<const float2*>(&bias[col]);
            v0.x += bb.x; v0.y += bb.y;
            v1.x += bb.x; v1.y += bb.y;
        }
        if (r_lo < N)
            *reinterpret_cast<float2*>(&C[r_lo * HID + col]) = v0;
        if (r_hi < N)
            *reinterpret_cast<float2*>(&C[r_hi * HID + col]) = v1;
    }
}

// ---------------- fused CSR SpMM: h = relu(agg + self + b), opt. pooling ----
__global__ void __launch_bounds__(256)
k_spmm(const float* __restrict__ bias, const int* __restrict__ bidx,
       int do_pool) {
    int gt = blockIdx.x * blockDim.x + threadIdx.x;
    int n  = gt >> 5;
    int l  = gt & 31;
    if (n >= NN) return;

    const float4* hw4 = reinterpret_cast<const float4*>(g_hw);
    float dn = g_dinv[n];
    int start = g_rowptr[n];
    int end   = g_rowptr[n + 1];

    float4 hv = hw4[n * 32 + l];
    float d2 = dn * dn;
    float4 acc = make_float4(hv.x * d2, hv.y * d2, hv.z * d2, hv.w * d2);

    for (int base = start; base < end; base += 32) {
        int idx = base + l;
        int s   = 0;
        float dv = 0.f;
        if (idx < end) {
            s  = g_csr[idx];
            dv = g_dinv[s] * dn;
        }
        int m = min(32, end - base);
        for (int j = 0; j < m; j++) {
            int   ss = __shfl_sync(0xffffffff, s, j);
            float nm = __shfl_sync(0xffffffff, dv, j);
            float4 v = hw4[ss * 32 + l];
            acc.x += v.x * nm; acc.y += v.y * nm;
            acc.z += v.z * nm; acc.w += v.w * nm;
        }
    }

    float4 bb = reinterpret_cast<const float4*>(bias)[l];
    acc.x = fmaxf(acc.x + bb.x, 0.f);
    acc.y = fmaxf(acc.y + bb.y, 0.f);
    acc.z = fmaxf(acc.z + bb.z, 0.f);
    acc.w = fmaxf(acc.w + bb.w, 0.f);
    reinterpret_cast<float4*>(g_h)[n * 32 + l] = acc;

    if (do_pool) {
        int g = bidx[n];
        red_add_f4(&g_pool[g * HID + l * 4], acc);
        if (l == 0) atomicAdd(&g_cnt[g], 1.f);
    }
}

// ---------------- output head ----------------------------------------------
__global__ void k_out(const float* __restrict__ Wo,
                      const float* __restrict__ bo,
                      float* __restrict__ out) {
    int t = blockIdx.x * blockDim.x + threadIdx.x;
    if (t >= NG * OD) return;
    int g = t / OD;
    int o = t % OD;
    float inv = 1.f / fmaxf(g_cnt[g], 1.f);
    float acc = 0.f;
#pragma unroll 8
    for (int k = 0; k < HID; k++)
        acc += g_pool[g * HID + k] * Wo[k * OD + o];
    out[t] = acc * inv + bo[o];
}

// ---------------- launch ----------------------------------------------------
extern "C" void kernel_launch(void* const* d_in, const int* in_sizes, int n_in,
                              void* d_out, int out_size) {
    const float* x    = (const float*)d_in[0];
    const int*   ei   = (const int*)d_in[1];
    const int*   bidx = (const int*)d_in[3];
    const float* We1  = (const float*)d_in[4];
    const float* be1  = (const float*)d_in[5];
    const float* We2  = (const float*)d_in[6];
    const float* be2  = (const float*)d_in[7];
    const float* Wg   = (const float*)d_in[8];
    const float* bg   = (const float*)d_in[9];
    const float* Wo   = (const float*)d_in[10];
    const float* bo   = (const float*)d_in[11];
    float*       out  = (float*)d_out;

    float *ph, *phw;
    cudaGetSymbolAddress((void**)&ph,  g_h);
    cudaGetSymbolAddress((void**)&phw, g_hw);

    const int TB = 256;
    const int GB = (NN + 127) / 128;
    // order chosen so launch #6 (ncu -s 5 -c 1) is a tensor GEMM
    k_zero  <<<(NG * HID + TB - 1) / TB, TB>>>();              // 0
    k_deg   <<<(NE + TB - 1) / TB, TB>>>(ei);                  // 1
    k_scan1 <<<NBLK, 1024>>>();                                // 2
    k_scan2 <<<1, 32>>>();                                     // 3
    k_embed1<<<(NN + 31) / 32, TB>>>(x, We1, be1);             // 4
    k_gemm_tc<<<GB, TB>>>(phw, We2, be2, ph, NN);              // 5 (profiled)
    k_scan3 <<<(NN + TB - 1) / TB, TB>>>();                    // 6
    k_fill  <<<(NE + TB - 1) / TB, TB>>>(ei);                  // 7
    for (int i = 0; i < NL; i++) {
        k_gemm_tc<<<GB, TB>>>(ph, Wg + i * HID * HID, nullptr, phw, NN);
        k_spmm<<<(NN * 32 + TB - 1) / TB, TB>>>(bg + i * HID, bidx,
                                                i == NL - 1 ? 1 : 0);
    }
    k_out<<<(NG * OD + TB - 1) / TB, TB>>>(Wo, bo, out);
}

// round 5
// speedup vs baseline: 4.0639x; 1.4352x over previous
#include <cuda_runtime.h>
#include <cuda_bf16.h>
#include <cstdint>

#define NN   50000
#define NE   800000
#define FEAT 16
#define HID  128
#define NL   4
#define NG   1024
#define OD   12
#define NBLK ((NN + 1023) / 1024)   // scan blocks = 49

// ---------------- scratch (device globals; no allocations allowed) ----------
__device__ float g_h[NN * HID];
__device__ float g_hw[NN * HID];
__device__ float g_dinv[NN];
__device__ float g_pool[NG * HID];
__device__ float g_cnt[NG];
__device__ int   g_degi[NN];
__device__ int   g_rowptr[NN + 1];
__device__ int   g_fillcnt[NN];
__device__ int   g_csr[NE];
__device__ int   g_bsum[64];

__device__ __forceinline__ void red_add_f4(float* p, float4 v) {
    asm volatile("red.global.add.v4.f32 [%0], {%1,%2,%3,%4};"
                 :: "l"(p), "f"(v.x), "f"(v.y), "f"(v.z), "f"(v.w)
                 : "memory");
}

__device__ __forceinline__ uint32_t smem_u32(const void* p) {
    uint32_t a;
    asm("{ .reg .u64 t; cvta.to.shared.u64 t, %1; cvt.u32.u64 %0, t; }"
        : "=r"(a) : "l"(p));
    return a;
}

// pack two floats to bf16x2: low 16 = x, high 16 = y
__device__ __forceinline__ uint32_t pack_bf16(float x, float y) {
    uint32_t r;
    asm("cvt.rn.bf16x2.f32 %0, %1, %2;" : "=r"(r) : "f"(y), "f"(x));
    return r;
}

__device__ __forceinline__ void ldsm_x4(uint32_t addr, uint32_t& r0,
                                        uint32_t& r1, uint32_t& r2, uint32_t& r3) {
    asm volatile("ldmatrix.sync.aligned.m8n8.x4.shared.b16 {%0,%1,%2,%3}, [%4];"
                 : "=r"(r0), "=r"(r1), "=r"(r2), "=r"(r3) : "r"(addr));
}
__device__ __forceinline__ void ldsm_x4_t(uint32_t addr, uint32_t& r0,
                                          uint32_t& r1, uint32_t& r2, uint32_t& r3) {
    asm volatile("ldmatrix.sync.aligned.m8n8.x4.trans.shared.b16 {%0,%1,%2,%3}, [%4];"
                 : "=r"(r0), "=r"(r1), "=r"(r2), "=r"(r3) : "r"(addr));
}

__device__ __forceinline__ void mma_bf16(float c[4],
                                         uint32_t a0, uint32_t a1,
                                         uint32_t a2, uint32_t a3,
                                         uint32_t b0, uint32_t b1) {
    asm volatile(
        "mma.sync.aligned.m16n8k16.row.col.f32.bf16.bf16.f32 "
        "{%0,%1,%2,%3}, {%4,%5,%6,%7}, {%8,%9}, {%0,%1,%2,%3};"
        : "+f"(c[0]), "+f"(c[1]), "+f"(c[2]), "+f"(c[3])
        : "r"(a0), "r"(a1), "r"(a2), "r"(a3), "r"(b0), "r"(b1));
}

// ---------------- init / CSR build -----------------------------------------
__global__ void k_zero() {
    int i = blockIdx.x * blockDim.x + threadIdx.x;
    if (i < NG * HID) g_pool[i] = 0.f;
    if (i < NG)       g_cnt[i]  = 0.f;
    if (i < NN) { g_degi[i] = 0; g_fillcnt[i] = 0; }
}

__global__ void k_deg(const int* __restrict__ ei) {
    int e = blockIdx.x * blockDim.x + threadIdx.x;
    if (e < NE) atomicAdd(&g_degi[ei[NE + e]], 1);
}

__global__ void __launch_bounds__(1024)
k_scan1() {
    __shared__ int sh[1024];
    int t = threadIdx.x;
    int i = blockIdx.x * 1024 + t;
    int d = (i < NN) ? g_degi[i] : 0;
    sh[t] = d;
    __syncthreads();
#pragma unroll
    for (int off = 1; off < 1024; off <<= 1) {
        int v = (t >= off) ? sh[t - off] : 0;
        __syncthreads();
        sh[t] += v;
        __syncthreads();
    }
    if (i < NN) g_rowptr[i] = sh[t];
    if (t == 1023) g_bsum[blockIdx.x] = sh[t];
}

__global__ void k_scan2() {
    if (threadIdx.x == 0) {
        int run = 0;
#pragma unroll
        for (int i = 0; i < NBLK; i++) {
            int v = g_bsum[i];
            g_bsum[i] = run;
            run += v;
        }
    }
}

__global__ void k_scan3() {
    int i = blockIdx.x * blockDim.x + threadIdx.x;
    if (i < NN) {
        int incl = g_rowptr[i];
        int d    = g_degi[i];
        g_rowptr[i] = incl - d + g_bsum[i >> 10];
        g_dinv[i]   = rsqrtf((float)d + 1.f);
    }
    if (i == 0) g_rowptr[NN] = NE;
}

__global__ void k_fill(const int* __restrict__ ei) {
    int e = blockIdx.x * blockDim.x + threadIdx.x;
    if (e >= NE) return;
    int s = ei[e];
    int d = ei[NE + e];
    int pos = g_rowptr[d] + atomicAdd(&g_fillcnt[d], 1);
    g_csr[pos] = s;
}

// ---------------- embed layer 1: hw = relu(x @ W_e1 + b_e1), K=16 ----------
__global__ void __launch_bounds__(256)
k_embed1(const float* __restrict__ x,
         const float* __restrict__ W,
         const float* __restrict__ b) {
    __shared__ float Ws[FEAT][HID];
    __shared__ float xs[32][FEAT];

    const int tid = threadIdx.x;
    const int n0  = blockIdx.x * 32;

    {
        const float4* Wv = reinterpret_cast<const float4*>(W);
        float4* Wsv = reinterpret_cast<float4*>(&Ws[0][0]);
        Wsv[tid]       = Wv[tid];
        Wsv[tid + 256] = Wv[tid + 256];
    }
    if (tid < 128) {
        int node = n0 + (tid >> 2);
        float4 v = make_float4(0.f, 0.f, 0.f, 0.f);
        if (node < NN)
            v = reinterpret_cast<const float4*>(x)[node * 4 + (tid & 3)];
        reinterpret_cast<float4*>(&xs[0][0])[tid] = v;
    }
    __syncthreads();

    const int rg = tid >> 4;
    const int cg = tid & 15;
    float acc[2][8];
    float bb[8];
#pragma unroll
    for (int j = 0; j < 8; j++) bb[j] = b[cg * 8 + j];
#pragma unroll
    for (int v = 0; v < 2; v++)
#pragma unroll
        for (int j = 0; j < 8; j++) acc[v][j] = bb[j];

#pragma unroll
    for (int k = 0; k < FEAT; k++) {
        float4 w0 = *reinterpret_cast<const float4*>(&Ws[k][cg * 8]);
        float4 w1 = *reinterpret_cast<const float4*>(&Ws[k][cg * 8 + 4]);
        float xv0 = xs[rg * 2 + 0][k];
        float xv1 = xs[rg * 2 + 1][k];
        acc[0][0] += xv0 * w0.x; acc[0][1] += xv0 * w0.y;
        acc[0][2] += xv0 * w0.z; acc[0][3] += xv0 * w0.w;
        acc[0][4] += xv0 * w1.x; acc[0][5] += xv0 * w1.y;
        acc[0][6] += xv0 * w1.z; acc[0][7] += xv0 * w1.w;
        acc[1][0] += xv1 * w0.x; acc[1][1] += xv1 * w0.y;
        acc[1][2] += xv1 * w0.z; acc[1][3] += xv1 * w0.w;
        acc[1][4] += xv1 * w1.x; acc[1][5] += xv1 * w1.y;
        acc[1][6] += xv1 * w1.z; acc[1][7] += xv1 * w1.w;
    }
#pragma unroll
    for (int v = 0; v < 2; v++) {
        int node = n0 + rg * 2 + v;
        if (node >= NN) continue;
        float4 o0 = make_float4(fmaxf(acc[v][0], 0.f), fmaxf(acc[v][1], 0.f),
                                fmaxf(acc[v][2], 0.f), fmaxf(acc[v][3], 0.f));
        float4 o1 = make_float4(fmaxf(acc[v][4], 0.f), fmaxf(acc[v][5], 0.f),
                                fmaxf(acc[v][6], 0.f), fmaxf(acc[v][7], 0.f));
        float4* out = reinterpret_cast<float4*>(&g_hw[node * HID + cg * 8]);
        out[0] = o0;
        out[1] = o1;
    }
}

// ---------------- bf16-split tensor-core GEMM: C = A@W (+bias) --------------
// Block 128x128, BK=32, 8 warps each m16 x n128. A,B split into bf16 hi/lo.
// A staged [m][k] (ldmatrix), B staged [k][n] (ldmatrix.trans).
#define APITCH 40    // ushorts: 80B rows -> LDSM banks (20r)%32 distinct
#define BPITCH 136   // ushorts: 272B rows -> LDSM banks (4r)%32 distinct

__global__ void __launch_bounds__(256, 2)
k_gemm_tc(const float* __restrict__ A, const float* __restrict__ W,
          const float* __restrict__ bias, float* __restrict__ C, int N) {
    __shared__ __align__(16) unsigned short sAh[128][APITCH];
    __shared__ __align__(16) unsigned short sAl[128][APITCH];
    __shared__ __align__(16) unsigned short sBh[32][BPITCH];
    __shared__ __align__(16) unsigned short sBl[32][BPITCH];

    const int tid  = threadIdx.x;
    const int wid  = tid >> 5;
    const int lane = tid & 31;
    const int grp  = lane >> 2;
    const int tig  = lane & 3;
    const int row0 = blockIdx.x * 128;
    const int wm   = wid * 16;

    float c[16][4];
#pragma unroll
    for (int i = 0; i < 16; i++)
#pragma unroll
        for (int j = 0; j < 4; j++) c[i][j] = 0.f;

    // per-thread staging indices
    // A: linear = tid + 256*j -> row = linear>>3 (0..127), f4 = linear&7
    // B: linear -> krow = linear>>5 (0..31), f4n = linear&31
    float4 ra[4], rb[4];

    auto load_chunk = [&](int kc, float4* va, float4* vb) {
#pragma unroll
        for (int j = 0; j < 4; j++) {
            int lin = tid + 256 * j;
            int r   = lin >> 3;
            int f4  = lin & 7;
            int row = row0 + r;
            va[j] = (row < N)
                  ? reinterpret_cast<const float4*>(A)[row * 32 + kc * 8 + f4]
                  : make_float4(0.f, 0.f, 0.f, 0.f);
            int kr  = lin >> 5;
            int f4n = lin & 31;
            vb[j] = reinterpret_cast<const float4*>(W)[(kc * 32 + kr) * 32 + f4n];
        }
    };

    auto store_chunk = [&](const float4* va, const float4* vb) {
#pragma unroll
        for (int j = 0; j < 4; j++) {
            int lin = tid + 256 * j;
            {   // A
                int r  = lin >> 3;
                int f4 = lin & 7;
                float4 v = va[j];
                uint32_t h01 = pack_bf16(v.x, v.y);
                uint32_t h23 = pack_bf16(v.z, v.w);
                float hx = __uint_as_float(h01 << 16);
                float hy = __uint_as_float(h01 & 0xffff0000u);
                float hz = __uint_as_float(h23 << 16);
                float hw = __uint_as_float(h23 & 0xffff0000u);
                uint32_t l01 = pack_bf16(v.x - hx, v.y - hy);
                uint32_t l23 = pack_bf16(v.z - hz, v.w - hw);
                *reinterpret_cast<uint2*>(&sAh[r][f4 * 4]) = make_uint2(h01, h23);
                *reinterpret_cast<uint2*>(&sAl[r][f4 * 4]) = make_uint2(l01, l23);
            }
            {   // B
                int kr  = lin >> 5;
                int f4n = lin & 31;
                float4 v = vb[j];
                uint32_t h01 = pack_bf16(v.x, v.y);
                uint32_t h23 = pack_bf16(v.z, v.w);
                float hx = __uint_as_float(h01 << 16);
                float hy = __uint_as_float(h01 & 0xffff0000u);
                float hz = __uint_as_float(h23 << 16);
                float hw = __uint_as_float(h23 & 0xffff0000u);
                uint32_t l01 = pack_bf16(v.x - hx, v.y - hy);
                uint32_t l23 = pack_bf16(v.z - hz, v.w - hw);
                *reinterpret_cast<uint2*>(&sBh[kr][f4n * 4]) = make_uint2(h01, h23);
                *reinterpret_cast<uint2*>(&sBl[kr][f4n * 4]) = make_uint2(l01, l23);
            }
        }
    };

    load_chunk(0, ra, rb);
    store_chunk(ra, rb);
    __syncthreads();

    // LDSM lane addresses (element offsets fixed per lane)
    const int a_row = wm + (lane & 15);
    const int a_c8  = (lane >> 4) * 8;                 // +0 / +8 within k16
    const int b_rf  = ((lane >> 3) & 1) * 8 + (lane & 7);  // row within k16
    const int b_c8  = (lane >> 4) * 8;                 // n offset within pair

    for (int kc = 0; kc < 4; kc++) {
        if (kc < 3) load_chunk(kc + 1, ra, rb);

#pragma unroll
        for (int ks = 0; ks < 2; ks++) {
            uint32_t ah0, ah1, ah2, ah3, al0, al1, al2, al3;
            ldsm_x4(smem_u32(&sAh[a_row][ks * 16 + a_c8]), ah0, ah1, ah2, ah3);
            ldsm_x4(smem_u32(&sAl[a_row][ks * 16 + a_c8]), al0, al1, al2, al3);

#pragma unroll
            for (int np = 0; np < 8; np++) {
                uint32_t bh0, bh1, bh2, bh3, bl0, bl1, bl2, bl3;
                ldsm_x4_t(smem_u32(&sBh[ks * 16 + b_rf][np * 16 + b_c8]),
                          bh0, bh1, bh2, bh3);
                ldsm_x4_t(smem_u32(&sBl[ks * 16 + b_rf][np * 16 + b_c8]),
                          bl0, bl1, bl2, bl3);
                mma_bf16(c[2 * np],     ah0, ah1, ah2, ah3, bl0, bl1);
                mma_bf16(c[2 * np],     al0, al1, al2, al3, bh0, bh1);
                mma_bf16(c[2 * np],     ah0, ah1, ah2, ah3, bh0, bh1);
                mma_bf16(c[2 * np + 1], ah0, ah1, ah2, ah3, bl2, bl3);
                mma_bf16(c[2 * np + 1], al0, al1, al2, al3, bh2, bh3);
                mma_bf16(c[2 * np + 1], ah0, ah1, ah2, ah3, bh2, bh3);
            }
        }

        if (kc < 3) {
            __syncthreads();
            store_chunk(ra, rb);
            __syncthreads();
        }
    }

    // epilogue: c[nt]: rows row0+wm+grp (+8), cols nt*8 + 2*tig (+1)
    int r_lo = row0 + wm + grp;
    int r_hi = r_lo + 8;
#pragma unroll
    for (int nt = 0; nt < 16; nt++) {
        int col = nt * 8 + 2 * tig;
        float2 v0 = make_float2(c[nt][0], c[nt][1]);
        float2 v1 = make_float2(c[nt][2], c[nt][3]);
        if (bias) {
            float2 bb = *reinterpret_cast<const float2*>(&bias[col]);
            v0.x += bb.x; v0.y += bb.y;
            v1.x += bb.x; v1.y += bb.y;
        }
        if (r_lo < N)
            *reinterpret_cast<float2*>(&C[r_lo * HID + col]) = v0;
        if (r_hi < N)
            *reinterpret_cast<float2*>(&C[r_hi * HID + col]) = v1;
    }
}

// ---------------- fused CSR SpMM: h = relu(agg + self + b), opt. pooling ----
__global__ void __launch_bounds__(256)
k_spmm(const float* __restrict__ bias, const int* __restrict__ bidx,
       int do_pool) {
    int gt = blockIdx.x * blockDim.x + threadIdx.x;
    int n  = gt >> 5;
    int l  = gt & 31;
    if (n >= NN) return;

    const float4* hw4 = reinterpret_cast<const float4*>(g_hw);
    float dn = g_dinv[n];
    int start = g_rowptr[n];
    int end   = g_rowptr[n + 1];

    float4 hv = hw4[n * 32 + l];
    float d2 = dn * dn;
    float4 acc = make_float4(hv.x * d2, hv.y * d2, hv.z * d2, hv.w * d2);

    for (int base = start; base < end; base += 32) {
        int idx = base + l;
        int s   = 0;
        float dv = 0.f;
        if (idx < end) {
            s  = g_csr[idx];
            dv = g_dinv[s] * dn;
        }
        int m = min(32, end - base);
        for (int j = 0; j < m; j++) {
            int   ss = __shfl_sync(0xffffffff, s, j);
            float nm = __shfl_sync(0xffffffff, dv, j);
            float4 v = hw4[ss * 32 + l];
            acc.x += v.x * nm; acc.y += v.y * nm;
            acc.z += v.z * nm; acc.w += v.w * nm;
        }
    }

    float4 bb = reinterpret_cast<const float4*>(bias)[l];
    acc.x = fmaxf(acc.x + bb.x, 0.f);
    acc.y = fmaxf(acc.y + bb.y, 0.f);
    acc.z = fmaxf(acc.z + bb.z, 0.f);
    acc.w = fmaxf(acc.w + bb.w, 0.f);
    reinterpret_cast<float4*>(g_h)[n * 32 + l] = acc;

    if (do_pool) {
        int g = bidx[n];
        red_add_f4(&g_pool[g * HID + l * 4], acc);
        if (l == 0) atomicAdd(&g_cnt[g], 1.f);
    }
}

// ---------------- output head ----------------------------------------------
__global__ void k_out(const float* __restrict__ Wo,
                      const float* __restrict__ bo,
                      float* __restrict__ out) {
    int t = blockIdx.x * blockDim.x + threadIdx.x;
    if (t >= NG * OD) return;
    int g = t / OD;
    int o = t % OD;
    float inv = 1.f / fmaxf(g_cnt[g], 1.f);
    float acc = 0.f;
#pragma unroll 8
    for (int k = 0; k < HID; k++)
        acc += g_pool[g * HID + k] * Wo[k * OD + o];
    out[t] = acc * inv + bo[o];
}

// ---------------- launch ----------------------------------------------------
extern "C" void kernel_launch(void* const* d_in, const int* in_sizes, int n_in,
                              void* d_out, int out_size) {
    const float* x    = (const float*)d_in[0];
    const int*   ei   = (const int*)d_in[1];
    const int*   bidx = (const int*)d_in[3];
    const float* We1  = (const float*)d_in[4];
    const float* be1  = (const float*)d_in[5];
    const float* We2  = (const float*)d_in[6];
    const float* be2  = (const float*)d_in[7];
    const float* Wg   = (const float*)d_in[8];
    const float* bg   = (const float*)d_in[9];
    const float* Wo   = (const float*)d_in[10];
    const float* bo   = (const float*)d_in[11];
    float*       out  = (float*)d_out;

    float *ph, *phw;
    cudaGetSymbolAddress((void**)&ph,  g_h);
    cudaGetSymbolAddress((void**)&phw, g_hw);

    const int TB = 256;
    const int GB = (NN + 127) / 128;
    k_zero  <<<(NG * HID + TB - 1) / TB, TB>>>();              // 0
    k_deg   <<<(NE + TB - 1) / TB, TB>>>(ei);                  // 1
    k_embed1<<<(NN + 31) / 32, TB>>>(x, We1, be1);             // 2
    k_gemm_tc<<<GB, TB>>>(phw, We2, be2, ph, NN);              // 3
    k_scan1 <<<NBLK, 1024>>>();                                // 4
    k_scan2 <<<1, 32>>>();                                     // 5
    k_scan3 <<<(NN + TB - 1) / TB, TB>>>();                    // 6
    k_fill  <<<(NE + TB - 1) / TB, TB>>>(ei);                  // 7
    for (int i = 0; i < NL; i++) {
        k_gemm_tc<<<GB, TB>>>(ph, Wg + i * HID * HID, nullptr, phw, NN);
        k_spmm<<<(NN * 32 + TB - 1) / TB, TB>>>(bg + i * HID, bidx,
                                                i == NL - 1 ? 1 : 0);
    }
    k_out<<<(NG * OD + TB - 1) / TB, TB>>>(Wo, bo, out);
}